// round 15
// baseline (speedup 1.0000x reference)
#include <cuda_runtime.h>
#include <math.h>

// Dataset is fixed: N=4000, E=64000, C=64
#define NMAX 4000
#define EMAX 64000
#define CHAN 64
#define NB 8
#define NY 9            // compact harmonics: ux,uy,uz,xx,xy,xz,yy,yz,zz
#define NKC 10          // compact A components: 1 + 3 + 6
#define NKP 12          // padded (16B-aligned rows in smem)

// ---------------- scratch (static device globals) ----------------------------
__device__ float g_ef[EMAX * NB];            // radial basis (edge order)
__device__ float g_Y[EMAX * NY];             // compact harmonics (edge order)
__device__ float g_efp[EMAX * NB];           // radial basis (sorted order)
__device__ float g_Yp[EMAX * NY];            // harmonics (sorted order)
__device__ int   g_srcp[EMAX];               // sorted position -> src node
__device__ int   g_dstp[EMAX];               // sorted position -> dst node
__device__ float g_A[NMAX * CHAN * NKC];     // node features A[n][c][k] compact
__device__ float g_h0a[NMAX * CHAN];
__device__ float g_h0b[NMAX * CHAN];
__device__ float g_h1[NMAX * 3 * CHAN];      // layout [n][k][c]
__device__ float g_h2[NMAX * 6 * CHAN];      // compact symmetric, layout [n][k][c]
__device__ float g_s[NMAX * CHAN];           // gate scalars
__device__ int   g_cnt[NMAX];                // histogram (self-restoring to 0)
__device__ int   g_cur[NMAX];                // atomic cursors
__device__ ulonglong2 g_wp[2 * 64 * 96];     // pre-packed broadcast W2 (w/16 in both lanes)

// packed f32x2 FMA (Blackwell)
__device__ __forceinline__ unsigned long long ffma2(unsigned long long a,
                                                    unsigned long long b,
                                                    unsigned long long c) {
    unsigned long long d;
    asm("fma.rn.f32x2 %0, %1, %2, %3;" : "=l"(d) : "l"(a), "l"(b), "l"(c));
    return d;
}
__device__ __forceinline__ unsigned long long pack2(float lo, float hi) {
    unsigned long long d;
    asm("mov.b64 %0, {%1, %2};" : "=l"(d) : "r"(__float_as_uint(lo)), "r"(__float_as_uint(hi)));
    return d;
}

// ---------------- fused setup: geometry + dst count | h0 + gate0 + zero A ----
__global__ void k_geomgate(const float* __restrict__ ev, const int* __restrict__ spec,
                           const float* __restrict__ Wemb, const float* __restrict__ Wg,
                           const int* __restrict__ eidx,
                           int E, int N, int GB_E, int GB_N) {
    if ((int)blockIdx.x < GB_E) {
        int e = blockIdx.x * blockDim.x + threadIdx.x;
        if (e >= E) return;
        float vx = ev[3 * e], vy = ev[3 * e + 1], vz = ev[3 * e + 2];
        float r = sqrtf(vx * vx + vy * vy + vz * vz);
        float inv = 1.f / r;
        float ux = vx * inv, uy = vy * inv, uz = vz * inv;
        float x = r * (1.f / 6.f);
        float fc = 0.f;
        if (x < 1.f) {
            float x2 = x * x;
            float x5 = x2 * x2 * x;
            fc = 1.f - 21.f * x5 + 35.f * x5 * x - 15.f * x5 * x2;
        }
        float pref = sqrtf(2.f / 6.f) * inv * fc;
        const float PI = 3.14159265358979323846f;
        float a = PI * x;
        float s1, c1;
        __sincosf(a, &s1, &c1);
        float twoc = 2.f * c1;
        float skm = 0.f, sk = s1;
        float* efp = g_ef + e * NB;
#pragma unroll
        for (int n = 0; n < NB; n++) {
            efp[n] = pref * sk;
            float nx = twoc * sk - skm;
            skm = sk; sk = nx;
        }
        float* Y = g_Y + e * NY;
        Y[0] = ux; Y[1] = uy; Y[2] = uz;
        Y[3] = ux * ux; Y[4] = ux * uy; Y[5] = ux * uz;
        Y[6] = uy * uy; Y[7] = uy * uz; Y[8] = uz * uz;
        atomicAdd(&g_cnt[eidx[E + e]], 1);
    } else {
        __shared__ float sh0[4][CHAN];
        int nb = blockIdx.x - GB_E;
        int g = threadIdx.x >> 6;
        int c = threadIdx.x & 63;
        int n = nb * 4 + g;
        int stride = GB_N * 256;
        for (int i = nb * 256 + threadIdx.x; i < N * CHAN * NKC; i += stride) g_A[i] = 0.f;
        if (n >= N) return;
        float h0 = Wemb[spec[n] * CHAN + c];
        g_h0a[n * CHAN + c] = h0;
        sh0[g][c] = h0;
        __syncthreads();
        float acc = 0.f;
#pragma unroll 8
        for (int d = 0; d < CHAN; d++) acc += sh0[g][d] * Wg[d * CHAN + c];
        g_s[n * CHAN + c] = acc;
    }
}

// ---------------- scan (+ weight packing); self-restores g_cnt=0 -------------
__global__ void k_scan(const float* __restrict__ rw2, int N) {
    // pack broadcast W2 weights (independent of scan): w' = w / 16 (AVG fold)
    for (int i = threadIdx.x; i < 2 * 64 * 96; i += 1024) {
        int l = i / (64 * 96);
        int r = i - l * 64 * 96;
        int j = r / 96, p = r - (r / 96) * 96;
        float wx = rw2[l * 64 * 256 + j * 256 + 2 * p] * 0.0625f;
        float wy = rw2[l * 64 * 256 + j * 256 + 2 * p + 1] * 0.0625f;
        ulonglong2 v;
        v.x = pack2(wx, wx);
        v.y = pack2(wy, wy);
        g_wp[i] = v;
    }
    __shared__ int sh[1024];
    __shared__ int carry_s;
    int t = threadIdx.x;
    if (t == 0) carry_s = 0;
    __syncthreads();
    int ntile = (N + 1023) / 1024;
    for (int tile = 0; tile < ntile; tile++) {
        int i = tile * 1024 + t;
        int v = (i < N) ? g_cnt[i] : 0;
        sh[t] = v;
        __syncthreads();
        for (int o = 1; o < 1024; o <<= 1) {
            int add = (t >= o) ? sh[t - o] : 0;
            __syncthreads();
            sh[t] += add;
            __syncthreads();
        }
        int incl = sh[t];
        int carry = carry_s;
        if (i < N) {
            g_cur[i] = carry + incl - v;   // exclusive prefix
            g_cnt[i] = 0;                  // restore for next call
        }
        __syncthreads();
        if (t == 1023) carry_s = carry + incl;
        __syncthreads();
    }
}

// place edges at sorted positions AND materialize ef/Y/src in sorted order
__global__ void k_place(const int* __restrict__ eidx, int E) {
    int e = blockIdx.x * blockDim.x + threadIdx.x;
    if (e >= E) return;
    int d = eidx[E + e];
    int pos = atomicAdd(&g_cur[d], 1);
    g_dstp[pos] = d;
    g_srcp[pos] = eidx[e];
    const float4* efs = (const float4*)(g_ef + e * NB);
    float4* efd = (float4*)(g_efp + (size_t)pos * NB);
    efd[0] = efs[0];
    efd[1] = efs[1];
    const float* ys = g_Y + e * NY;
    float* yd = g_Yp + (size_t)pos * NY;
#pragma unroll
    for (int k = 0; k < NY; k++) yd[k] = ys[k];
}

// fused edge kernel. Block = 32 sorted positions, 384 threads, 2 barriers.
// Phase 3: thread = (column-pair p, edge-octet g); pre-packed weights (1/16 folded).
__global__ void __launch_bounds__(384, 3) k_edge(
        const float* __restrict__ rw1, int E, int layer) {
    __shared__ __align__(16) float shH[64][36];  // hidden [j][edge]
    __shared__ float shS[32][64];                // s_e [edge][c]
    __shared__ float shYc[32][NY];               // compact harmonics per edge
    __shared__ __align__(16) float shEf[32][NB]; // staged radial basis
    __shared__ int   shSrc[32];
    __shared__ int   shDst[32];
    int p0 = blockIdx.x * 32;
    int tid = threadIdx.x;
    const float* W1 = rw1 + layer * NB * CHAN;

    // contiguous staging (no index dependency)
    if (tid < 32) {
        shSrc[tid] = g_srcp[p0 + tid];
        shDst[tid] = g_dstp[p0 + tid];
    }
    if (tid >= 64 && tid < 320) {
        int t = tid - 64;
        shEf[t >> 3][t & 7] = g_efp[(size_t)p0 * NB + t];
    }
    for (int i = tid; i < 32 * NY; i += 384) {
        shYc[i / NY][i % NY] = g_Yp[(size_t)p0 * NY + i];
    }
    __syncthreads();

    // phases 1+2 over (el, c)
    for (int idx = tid; idx < 32 * CHAN; idx += 384) {
        int c = idx & 63;
        int el = idx >> 6;
        float h = 0.f;
#pragma unroll
        for (int i = 0; i < NB; i++) h += shEf[el][i] * W1[i * CHAN + c];
        h = h * (1.f / (1.f + __expf(-h)));   // silu
        shH[c][el] = h;

        int src = shSrc[el];
        float se = g_s[src * CHAN + c];
        if (layer > 0) {
            const float* y = shYc[el];
            const float* h1 = g_h1 + src * 3 * CHAN + c;
            se += h1[0] * y[0] + h1[CHAN] * y[1] + h1[2 * CHAN] * y[2];
            const float* h2 = g_h2 + src * 6 * CHAN + c;
            se += h2[0] * y[3] + 2.f * h2[CHAN] * y[4] + 2.f * h2[2 * CHAN] * y[5]
                + h2[3 * CHAN] * y[6] + 2.f * h2[4 * CHAN] * y[7] + h2[5 * CHAN] * y[8];
        }
        shS[el][c] = se;
    }
    __syncthreads();

    // phase 3
    {
        int p = tid % 96;           // column pair: cidx = 2p, 2p+1
        int g = tid / 96;           // edge octet
        int eb0 = g * 8;
        int c0 = (2 * p) & 63;
        int c1 = c0 + 1;
        int L = p >> 5;             // 0,1,2 (warp-uniform)
        const ulonglong2* wp = g_wp + layer * 64 * 96 + p;

        unsigned long long acc[2][4];
#pragma unroll
        for (int m = 0; m < 4; m++) { acc[0][m] = 0ull; acc[1][m] = 0ull; }

#pragma unroll
        for (int jb = 0; jb < 64; jb += 4) {
            ulonglong2 wv[4];
#pragma unroll
            for (int u = 0; u < 4; u++)
                wv[u] = wp[(jb + u) * 96];
#pragma unroll
            for (int u = 0; u < 4; u++) {
                const double2* dp = (const double2*)&shH[jb + u][eb0];
                double2 d0 = dp[0], d1 = dp[1];
                unsigned long long e01 = __double_as_longlong(d0.x);
                unsigned long long e23 = __double_as_longlong(d0.y);
                unsigned long long e45 = __double_as_longlong(d1.x);
                unsigned long long e67 = __double_as_longlong(d1.y);
                acc[0][0] = ffma2(e01, wv[u].x, acc[0][0]);
                acc[0][1] = ffma2(e23, wv[u].x, acc[0][1]);
                acc[0][2] = ffma2(e45, wv[u].x, acc[0][2]);
                acc[0][3] = ffma2(e67, wv[u].x, acc[0][3]);
                acc[1][0] = ffma2(e01, wv[u].y, acc[1][0]);
                acc[1][1] = ffma2(e23, wv[u].y, acc[1][1]);
                acc[1][2] = ffma2(e45, wv[u].y, acc[1][2]);
                acc[1][3] = ffma2(e67, wv[u].y, acc[1][3]);
            }
        }
        // unpack messages for both columns (1/16 already folded into weights)
        float z0[8], z1[8];
#pragma unroll
        for (int m = 0; m < 4; m++) {
            int ea = eb0 + 2 * m, eb = ea + 1;
            z0[2 * m]     = __uint_as_float((unsigned)(acc[0][m] & 0xffffffffull)) * shS[ea][c0];
            z0[2 * m + 1] = __uint_as_float((unsigned)(acc[0][m] >> 32)) * shS[eb][c0];
            z1[2 * m]     = __uint_as_float((unsigned)(acc[1][m] & 0xffffffffull)) * shS[ea][c1];
            z1[2 * m + 1] = __uint_as_float((unsigned)(acc[1][m] >> 32)) * shS[eb][c1];
        }

        // scatter-reduce runs of equal dst over the 8-edge octet, both columns
        float* A0 = g_A + (size_t)c0 * NKC;
        float* A1 = g_A + (size_t)c1 * NKC;
        if (L == 0) {
            float s0 = 0.f, s1 = 0.f;
            int cur = shDst[eb0];
#pragma unroll
            for (int i = 0; i < 8; i++) {
                int d = shDst[eb0 + i];
                if (d != cur) {
                    size_t b = (size_t)cur * CHAN * NKC;
                    atomicAdd(&A0[b], s0);
                    atomicAdd(&A1[b], s1);
                    s0 = 0.f; s1 = 0.f; cur = d;
                }
                s0 += z0[i]; s1 += z1[i];
            }
            size_t b = (size_t)cur * CHAN * NKC;
            atomicAdd(&A0[b], s0);
            atomicAdd(&A1[b], s1);
        } else if (L == 1) {
            float s0[3] = {0.f, 0.f, 0.f}, s1[3] = {0.f, 0.f, 0.f};
            int cur = shDst[eb0];
#pragma unroll
            for (int i = 0; i < 8; i++) {
                int el = eb0 + i;
                int d = shDst[el];
                if (d != cur) {
                    size_t b = (size_t)cur * CHAN * NKC + 1;
#pragma unroll
                    for (int k = 0; k < 3; k++) {
                        atomicAdd(&A0[b + k], s0[k]);
                        atomicAdd(&A1[b + k], s1[k]);
                        s0[k] = 0.f; s1[k] = 0.f;
                    }
                    cur = d;
                }
                float za = z0[i], zb = z1[i];
#pragma unroll
                for (int k = 0; k < 3; k++) {
                    float yv = shYc[el][k];
                    s0[k] += za * yv; s1[k] += zb * yv;
                }
            }
            size_t b = (size_t)cur * CHAN * NKC + 1;
#pragma unroll
            for (int k = 0; k < 3; k++) {
                atomicAdd(&A0[b + k], s0[k]);
                atomicAdd(&A1[b + k], s1[k]);
            }
        } else {
            float s0[6], s1[6];
#pragma unroll
            for (int k = 0; k < 6; k++) { s0[k] = 0.f; s1[k] = 0.f; }
            int cur = shDst[eb0];
#pragma unroll
            for (int i = 0; i < 8; i++) {
                int el = eb0 + i;
                int d = shDst[el];
                if (d != cur) {
                    size_t b = (size_t)cur * CHAN * NKC + 4;
#pragma unroll
                    for (int k = 0; k < 6; k++) {
                        atomicAdd(&A0[b + k], s0[k]);
                        atomicAdd(&A1[b + k], s1[k]);
                        s0[k] = 0.f; s1[k] = 0.f;
                    }
                    cur = d;
                }
                float za = z0[i], zb = z1[i];
#pragma unroll
                for (int k = 0; k < 6; k++) {
                    float yv = shYc[el][3 + k];
                    s0[k] += za * yv; s1[k] += zb * yv;
                }
            }
            size_t b = (size_t)cur * CHAN * NKC + 4;
#pragma unroll
            for (int k = 0; k < 6; k++) {
                atomicAdd(&A0[b + k], s0[k]);
                atomicAdd(&A1[b + k], s1[k]);
            }
        }
    }
}

// self-contraction + output; layer 0 also computes the layer-1 gate (fused k_gate).
// Layer-0 mixing GEMV uses packed f32x2 over padded sA rows.
__global__ void k_update(const float* __restrict__ Wmix, const float* __restrict__ Wsc,
                         const float* __restrict__ Wg,
                         const int* __restrict__ spec, float* __restrict__ out,
                         int layer, int N) {
    __shared__ __align__(16) float sA[CHAN * NKP];   // padded rows (48B, 16B-aligned)
    __shared__ float sh_o0[CHAN];
    int n = blockIdx.x;
    int d = threadIdx.x;
    for (int i = d; i < CHAN * NKC; i += CHAN) {
        int c = i / NKC, k = i - c * NKC;
        sA[c * NKP + k] = g_A[n * CHAN * NKC + i];
    }
    __syncthreads();
    for (int i = d; i < CHAN * NKC; i += CHAN) g_A[n * CHAN * NKC + i] = 0.f;

    const float* h0in = (layer == 0) ? g_h0a : g_h0b;
    float* h0out = (layer == 0) ? g_h0b : g_h0a;

    float A0d = sA[d * NKP];
    float A1d[3], A2c[6];
#pragma unroll
    for (int k = 0; k < 3; k++) A1d[k] = sA[d * NKP + 1 + k];
#pragma unroll
    for (int k = 0; k < 6; k++) A2c[k] = sA[d * NKP + 4 + k];

    const float* Wm = Wmix + layer * 3 * CHAN * CHAN;
    float mat0 = 0.f;
    float mat1[3] = {0.f, 0.f, 0.f};
    float mat2[6] = {0.f, 0.f, 0.f, 0.f, 0.f, 0.f};
    if (layer == 0) {
        // packed: pairs (k0,k1)(k2,k3)(k4,k5)(k6,k7)(k8,k9)
        unsigned long long a01 = 0ull, a23 = 0ull, a45 = 0ull, a67 = 0ull, a89 = 0ull;
        for (int c = 0; c < CHAN; c++) {
            const double2* rp = (const double2*)&sA[c * NKP];
            double2 r03 = rp[0];            // k0..k3
            double2 r47 = rp[1];            // k4..k7
            unsigned long long r89 = *(const unsigned long long*)&sA[c * NKP + 8];
            float w0 = Wm[c * CHAN + d];
            float w1 = Wm[CHAN * CHAN + c * CHAN + d];
            float w2 = Wm[2 * CHAN * CHAN + c * CHAN + d];
            unsigned long long w01 = pack2(w0, w1);
            unsigned long long w11 = pack2(w1, w1);
            unsigned long long w22 = pack2(w2, w2);
            a01 = ffma2(__double_as_longlong(r03.x), w01, a01);
            a23 = ffma2(__double_as_longlong(r03.y), w11, a23);
            a45 = ffma2(__double_as_longlong(r47.x), w22, a45);
            a67 = ffma2(__double_as_longlong(r47.y), w22, a67);
            a89 = ffma2(r89, w22, a89);
        }
        mat0    = __uint_as_float((unsigned)(a01 & 0xffffffffull));
        mat1[0] = __uint_as_float((unsigned)(a01 >> 32));
        mat1[1] = __uint_as_float((unsigned)(a23 & 0xffffffffull));
        mat1[2] = __uint_as_float((unsigned)(a23 >> 32));
        mat2[0] = __uint_as_float((unsigned)(a45 & 0xffffffffull));
        mat2[1] = __uint_as_float((unsigned)(a45 >> 32));
        mat2[2] = __uint_as_float((unsigned)(a67 & 0xffffffffull));
        mat2[3] = __uint_as_float((unsigned)(a67 >> 32));
        mat2[4] = __uint_as_float((unsigned)(a89 & 0xffffffffull));
        mat2[5] = __uint_as_float((unsigned)(a89 >> 32));
    } else {
        for (int c = 0; c < CHAN; c++)
            mat0 += sA[c * NKP] * Wm[c * CHAN + d];
    }
    float sq = A1d[0] * A1d[0] + A1d[1] * A1d[1] + A1d[2] * A1d[2]
             + A2c[0] * A2c[0] + A2c[3] * A2c[3] + A2c[5] * A2c[5]
             + 2.f * (A2c[1] * A2c[1] + A2c[2] * A2c[2] + A2c[4] * A2c[4]);

    int sp = spec[n];
    float sc0 = Wsc[layer * 10 * CHAN + sp * CHAN + d] * h0in[n * CHAN + d];
    float o0 = mat0 + sq + sc0;
    out[n * 128 + layer * CHAN + d] = o0;
    h0out[n * CHAN + d] = o0;

    if (layer == 0) {
        float m00 = A2c[0], m01 = A2c[1], m02 = A2c[2];
        float m11 = A2c[3], m12 = A2c[4], m22 = A2c[5];
        float v0 = mat1[0] + A0d * A1d[0] + m00 * A1d[0] + m01 * A1d[1] + m02 * A1d[2];
        float v1 = mat1[1] + A0d * A1d[1] + m01 * A1d[0] + m11 * A1d[1] + m12 * A1d[2];
        float v2 = mat1[2] + A0d * A1d[2] + m02 * A1d[0] + m12 * A1d[1] + m22 * A1d[2];
        g_h1[n * 3 * CHAN + 0 * CHAN + d] = v0;
        g_h1[n * 3 * CHAN + 1 * CHAN + d] = v1;
        g_h1[n * 3 * CHAN + 2 * CHAN + d] = v2;
        g_h2[n * 6 * CHAN + 0 * CHAN + d] = mat2[0] + A1d[0] * A1d[0] + A0d * m00;
        g_h2[n * 6 * CHAN + 1 * CHAN + d] = mat2[1] + A1d[0] * A1d[1] + A0d * m01;
        g_h2[n * 6 * CHAN + 2 * CHAN + d] = mat2[2] + A1d[0] * A1d[2] + A0d * m02;
        g_h2[n * 6 * CHAN + 3 * CHAN + d] = mat2[3] + A1d[1] * A1d[1] + A0d * m11;
        g_h2[n * 6 * CHAN + 4 * CHAN + d] = mat2[4] + A1d[1] * A1d[2] + A0d * m12;
        g_h2[n * 6 * CHAN + 5 * CHAN + d] = mat2[5] + A1d[2] * A1d[2] + A0d * m22;

        // fused gate for layer 1: s = o0(block) @ Wg[1]
        sh_o0[d] = o0;
        __syncthreads();
        const float* W = Wg + CHAN * CHAN;
        float acc = 0.f;
#pragma unroll 8
        for (int dd = 0; dd < CHAN; dd++) acc += sh_o0[dd] * W[dd * CHAN + d];
        g_s[n * CHAN + d] = acc;
    }
}

// ---------------- launch -----------------------------------------------------
extern "C" void kernel_launch(void* const* d_in, const int* in_sizes, int n_in,
                              void* d_out, int out_size) {
    const float* edge_vec = (const float*)d_in[0];
    const int*   species  = (const int*)d_in[1];
    const int*   eidx     = (const int*)d_in[2];
    const float* W_emb    = (const float*)d_in[3];
    const float* rw1      = (const float*)d_in[4];
    const float* rw2      = (const float*)d_in[5];
    const float* Wg       = (const float*)d_in[6];
    const float* Wsc      = (const float*)d_in[7];
    const float* Wmix     = (const float*)d_in[8];
    float* out = (float*)d_out;

    int E = in_sizes[0] / 3;
    int N = in_sizes[1];
    int GB_E = (E + 255) / 256;
    int GB_N = (N + 3) / 4;

    k_geomgate<<<GB_E + GB_N, 256>>>(edge_vec, species, W_emb, Wg, eidx,
                                     E, N, GB_E, GB_N);                    // 0
    k_scan<<<1, 1024>>>(rw2, N);                                           // 1
    k_place<<<GB_E, 256>>>(eidx, E);                                       // 2

    k_edge<<<E / 32, 384>>>(rw1, E, 0);                                    // 3 <- profiled
    k_update<<<N, CHAN>>>(Wmix, Wsc, Wg, species, out, 0, N);              // 4
    k_edge<<<E / 32, 384>>>(rw1, E, 1);                                    // 5
    k_update<<<N, CHAN>>>(Wmix, Wsc, Wg, species, out, 1, N);              // 6
}

// round 16
// speedup vs baseline: 1.1168x; 1.1168x over previous
#include <cuda_runtime.h>
#include <math.h>

// Dataset is fixed: N=4000, E=64000, C=64
#define NMAX 4000
#define EMAX 64000
#define CHAN 64
#define NB 8
#define NY 9            // compact harmonics: ux,uy,uz,xx,xy,xz,yy,yz,zz
#define NKC 10          // compact A components: 1 + 3 + 6
#define NKP 12          // padded (16B-aligned rows in smem)

// ---------------- scratch (static device globals) ----------------------------
__device__ float g_ef[EMAX * NB];            // radial basis (edge order)
__device__ float g_Y[EMAX * NY];             // compact harmonics (edge order)
__device__ float g_efp[EMAX * NB];           // radial basis (sorted order)
__device__ float g_Yp[EMAX * NY];            // harmonics (sorted order)
__device__ int   g_srcp[EMAX];               // sorted position -> src node
__device__ int   g_dstp[EMAX];               // sorted position -> dst node
__device__ float g_A[NMAX * CHAN * NKC];     // node features A[n][c][k] compact
__device__ float g_h0a[NMAX * CHAN];
__device__ float g_h0b[NMAX * CHAN];
__device__ float g_h1[NMAX * 3 * CHAN];      // layout [n][k][c]
__device__ float g_h2[NMAX * 6 * CHAN];      // compact symmetric, layout [n][k][c]
__device__ float g_s[NMAX * CHAN];           // gate scalars
__device__ int   g_cnt[NMAX];                // histogram (self-restoring to 0)
__device__ int   g_cur[NMAX];                // atomic cursors

// packed f32x2 FMA (Blackwell)
__device__ __forceinline__ unsigned long long ffma2(unsigned long long a,
                                                    unsigned long long b,
                                                    unsigned long long c) {
    unsigned long long d;
    asm("fma.rn.f32x2 %0, %1, %2, %3;" : "=l"(d) : "l"(a), "l"(b), "l"(c));
    return d;
}
__device__ __forceinline__ unsigned long long pack2(float lo, float hi) {
    unsigned long long d;
    asm("mov.b64 %0, {%1, %2};" : "=l"(d) : "r"(__float_as_uint(lo)), "r"(__float_as_uint(hi)));
    return d;
}

// ---------------- fused setup: geometry + dst count | h0 + gate0 + zero A ----
__global__ void k_geomgate(const float* __restrict__ ev, const int* __restrict__ spec,
                           const float* __restrict__ Wemb, const float* __restrict__ Wg,
                           const int* __restrict__ eidx,
                           int E, int N, int GB_E, int GB_N) {
    if ((int)blockIdx.x < GB_E) {
        int e = blockIdx.x * blockDim.x + threadIdx.x;
        if (e >= E) return;
        float vx = ev[3 * e], vy = ev[3 * e + 1], vz = ev[3 * e + 2];
        float r = sqrtf(vx * vx + vy * vy + vz * vz);
        float inv = 1.f / r;
        float ux = vx * inv, uy = vy * inv, uz = vz * inv;
        float x = r * (1.f / 6.f);
        float fc = 0.f;
        if (x < 1.f) {
            float x2 = x * x;
            float x5 = x2 * x2 * x;
            fc = 1.f - 21.f * x5 + 35.f * x5 * x - 15.f * x5 * x2;
        }
        float pref = sqrtf(2.f / 6.f) * inv * fc;
        const float PI = 3.14159265358979323846f;
        float a = PI * x;
        float s1, c1;
        __sincosf(a, &s1, &c1);
        float twoc = 2.f * c1;
        float skm = 0.f, sk = s1;
        float* efp = g_ef + e * NB;
#pragma unroll
        for (int n = 0; n < NB; n++) {
            efp[n] = pref * sk;
            float nx = twoc * sk - skm;
            skm = sk; sk = nx;
        }
        float* Y = g_Y + e * NY;
        Y[0] = ux; Y[1] = uy; Y[2] = uz;
        Y[3] = ux * ux; Y[4] = ux * uy; Y[5] = ux * uz;
        Y[6] = uy * uy; Y[7] = uy * uz; Y[8] = uz * uz;
        atomicAdd(&g_cnt[eidx[E + e]], 1);
    } else {
        __shared__ float sh0[4][CHAN];
        int nb = blockIdx.x - GB_E;
        int g = threadIdx.x >> 6;
        int c = threadIdx.x & 63;
        int n = nb * 4 + g;
        int stride = GB_N * 256;
        for (int i = nb * 256 + threadIdx.x; i < N * CHAN * NKC; i += stride) g_A[i] = 0.f;
        if (n >= N) return;
        float h0 = Wemb[spec[n] * CHAN + c];
        g_h0a[n * CHAN + c] = h0;
        sh0[g][c] = h0;
        __syncthreads();
        float acc = 0.f;
#pragma unroll 8
        for (int d = 0; d < CHAN; d++) acc += sh0[g][d] * Wg[d * CHAN + c];
        g_s[n * CHAN + c] = acc;
    }
}

// ---------------- exclusive scan of g_cnt -> g_cur; self-restore g_cnt=0 -----
__global__ void k_scan(int N) {
    __shared__ int sh[1024];
    __shared__ int carry_s;
    int t = threadIdx.x;
    if (t == 0) carry_s = 0;
    __syncthreads();
    int ntile = (N + 1023) / 1024;
    for (int tile = 0; tile < ntile; tile++) {
        int i = tile * 1024 + t;
        int v = (i < N) ? g_cnt[i] : 0;
        sh[t] = v;
        __syncthreads();
        for (int o = 1; o < 1024; o <<= 1) {
            int add = (t >= o) ? sh[t - o] : 0;
            __syncthreads();
            sh[t] += add;
            __syncthreads();
        }
        int incl = sh[t];
        int carry = carry_s;
        if (i < N) {
            g_cur[i] = carry + incl - v;   // exclusive prefix
            g_cnt[i] = 0;                  // restore for next call
        }
        __syncthreads();
        if (t == 1023) carry_s = carry + incl;
        __syncthreads();
    }
}

// place edges at sorted positions AND materialize ef/Y/src in sorted order
__global__ void k_place(const int* __restrict__ eidx, int E) {
    int e = blockIdx.x * blockDim.x + threadIdx.x;
    if (e >= E) return;
    int d = eidx[E + e];
    int pos = atomicAdd(&g_cur[d], 1);
    g_dstp[pos] = d;
    g_srcp[pos] = eidx[e];
    const float4* efs = (const float4*)(g_ef + e * NB);
    float4* efd = (float4*)(g_efp + (size_t)pos * NB);
    efd[0] = efs[0];
    efd[1] = efs[1];
    const float* ys = g_Y + e * NY;
    float* yd = g_Yp + (size_t)pos * NY;
#pragma unroll
    for (int k = 0; k < NY; k++) yd[k] = ys[k];
}

// fused edge kernel. Block = 32 sorted positions, 384 threads, 2 barriers.
// Phase 3 (round-14 proven shape): thread = (column-pair p, edge-octet g);
// float2 weight loads + mov.b64 broadcast packing. 1/AVG folded into shS.
__global__ void __launch_bounds__(384, 3) k_edge(
        const float* __restrict__ rw1, const float* __restrict__ rw2,
        int E, int layer) {
    __shared__ __align__(16) float shH[64][36];  // hidden [j][edge]
    __shared__ float shS[32][64];                // s_e/16 [edge][c]
    __shared__ float shYc[32][NY];               // compact harmonics per edge
    __shared__ __align__(16) float shEf[32][NB]; // staged radial basis
    __shared__ int   shSrc[32];
    __shared__ int   shDst[32];
    int p0 = blockIdx.x * 32;
    int tid = threadIdx.x;
    const float* W1 = rw1 + layer * NB * CHAN;

    // contiguous staging (no index dependency)
    if (tid < 32) {
        shSrc[tid] = g_srcp[p0 + tid];
        shDst[tid] = g_dstp[p0 + tid];
    }
    if (tid >= 64 && tid < 320) {
        int t = tid - 64;
        shEf[t >> 3][t & 7] = g_efp[(size_t)p0 * NB + t];
    }
    for (int i = tid; i < 32 * NY; i += 384) {
        shYc[i / NY][i % NY] = g_Yp[(size_t)p0 * NY + i];
    }
    __syncthreads();

    // phases 1+2 over (el, c); store se/16
    for (int idx = tid; idx < 32 * CHAN; idx += 384) {
        int c = idx & 63;
        int el = idx >> 6;
        float h = 0.f;
#pragma unroll
        for (int i = 0; i < NB; i++) h += shEf[el][i] * W1[i * CHAN + c];
        h = h * (1.f / (1.f + __expf(-h)));   // silu
        shH[c][el] = h;

        int src = shSrc[el];
        float se = g_s[src * CHAN + c];
        if (layer > 0) {
            const float* y = shYc[el];
            const float* h1 = g_h1 + src * 3 * CHAN + c;
            se += h1[0] * y[0] + h1[CHAN] * y[1] + h1[2 * CHAN] * y[2];
            const float* h2 = g_h2 + src * 6 * CHAN + c;
            se += h2[0] * y[3] + 2.f * h2[CHAN] * y[4] + 2.f * h2[2 * CHAN] * y[5]
                + h2[3 * CHAN] * y[6] + 2.f * h2[4 * CHAN] * y[7] + h2[5 * CHAN] * y[8];
        }
        shS[el][c] = se * 0.0625f;   // fold 1/AVG here
    }
    __syncthreads();

    // phase 3
    {
        int p = tid % 96;           // column pair: cidx = 2p, 2p+1
        int g = tid / 96;           // edge octet
        int eb0 = g * 8;
        int c0 = (2 * p) & 63;
        int c1 = c0 + 1;
        int L = p >> 5;             // 0,1,2 (warp-uniform)
        const float* w2base = rw2 + layer * CHAN * 256 + 2 * p;

        unsigned long long acc[2][4];
#pragma unroll
        for (int m = 0; m < 4; m++) { acc[0][m] = 0ull; acc[1][m] = 0ull; }

#pragma unroll
        for (int jb = 0; jb < 64; jb += 4) {
            float2 wv[4];
#pragma unroll
            for (int u = 0; u < 4; u++)
                wv[u] = *(const float2*)&w2base[(jb + u) * 256];
#pragma unroll
            for (int u = 0; u < 4; u++) {
                unsigned long long wx, wy;
                asm("mov.b64 %0, {%1, %1};" : "=l"(wx) : "r"(__float_as_uint(wv[u].x)));
                asm("mov.b64 %0, {%1, %1};" : "=l"(wy) : "r"(__float_as_uint(wv[u].y)));
                const double2* dp = (const double2*)&shH[jb + u][eb0];
                double2 d0 = dp[0], d1 = dp[1];
                unsigned long long e01 = __double_as_longlong(d0.x);
                unsigned long long e23 = __double_as_longlong(d0.y);
                unsigned long long e45 = __double_as_longlong(d1.x);
                unsigned long long e67 = __double_as_longlong(d1.y);
                acc[0][0] = ffma2(e01, wx, acc[0][0]);
                acc[0][1] = ffma2(e23, wx, acc[0][1]);
                acc[0][2] = ffma2(e45, wx, acc[0][2]);
                acc[0][3] = ffma2(e67, wx, acc[0][3]);
                acc[1][0] = ffma2(e01, wy, acc[1][0]);
                acc[1][1] = ffma2(e23, wy, acc[1][1]);
                acc[1][2] = ffma2(e45, wy, acc[1][2]);
                acc[1][3] = ffma2(e67, wy, acc[1][3]);
            }
        }
        // unpack messages for both columns (1/16 already folded into shS)
        float z0[8], z1[8];
#pragma unroll
        for (int m = 0; m < 4; m++) {
            int ea = eb0 + 2 * m, eb = ea + 1;
            z0[2 * m]     = __uint_as_float((unsigned)(acc[0][m] & 0xffffffffull)) * shS[ea][c0];
            z0[2 * m + 1] = __uint_as_float((unsigned)(acc[0][m] >> 32)) * shS[eb][c0];
            z1[2 * m]     = __uint_as_float((unsigned)(acc[1][m] & 0xffffffffull)) * shS[ea][c1];
            z1[2 * m + 1] = __uint_as_float((unsigned)(acc[1][m] >> 32)) * shS[eb][c1];
        }

        // scatter-reduce runs of equal dst over the 8-edge octet, both columns
        float* A0 = g_A + (size_t)c0 * NKC;
        float* A1 = g_A + (size_t)c1 * NKC;
        if (L == 0) {
            float s0 = 0.f, s1 = 0.f;
            int cur = shDst[eb0];
#pragma unroll
            for (int i = 0; i < 8; i++) {
                int d = shDst[eb0 + i];
                if (d != cur) {
                    size_t b = (size_t)cur * CHAN * NKC;
                    atomicAdd(&A0[b], s0);
                    atomicAdd(&A1[b], s1);
                    s0 = 0.f; s1 = 0.f; cur = d;
                }
                s0 += z0[i]; s1 += z1[i];
            }
            size_t b = (size_t)cur * CHAN * NKC;
            atomicAdd(&A0[b], s0);
            atomicAdd(&A1[b], s1);
        } else if (L == 1) {
            float s0[3] = {0.f, 0.f, 0.f}, s1[3] = {0.f, 0.f, 0.f};
            int cur = shDst[eb0];
#pragma unroll
            for (int i = 0; i < 8; i++) {
                int el = eb0 + i;
                int d = shDst[el];
                if (d != cur) {
                    size_t b = (size_t)cur * CHAN * NKC + 1;
#pragma unroll
                    for (int k = 0; k < 3; k++) {
                        atomicAdd(&A0[b + k], s0[k]);
                        atomicAdd(&A1[b + k], s1[k]);
                        s0[k] = 0.f; s1[k] = 0.f;
                    }
                    cur = d;
                }
                float za = z0[i], zb = z1[i];
#pragma unroll
                for (int k = 0; k < 3; k++) {
                    float yv = shYc[el][k];
                    s0[k] += za * yv; s1[k] += zb * yv;
                }
            }
            size_t b = (size_t)cur * CHAN * NKC + 1;
#pragma unroll
            for (int k = 0; k < 3; k++) {
                atomicAdd(&A0[b + k], s0[k]);
                atomicAdd(&A1[b + k], s1[k]);
            }
        } else {
            float s0[6], s1[6];
#pragma unroll
            for (int k = 0; k < 6; k++) { s0[k] = 0.f; s1[k] = 0.f; }
            int cur = shDst[eb0];
#pragma unroll
            for (int i = 0; i < 8; i++) {
                int el = eb0 + i;
                int d = shDst[el];
                if (d != cur) {
                    size_t b = (size_t)cur * CHAN * NKC + 4;
#pragma unroll
                    for (int k = 0; k < 6; k++) {
                        atomicAdd(&A0[b + k], s0[k]);
                        atomicAdd(&A1[b + k], s1[k]);
                        s0[k] = 0.f; s1[k] = 0.f;
                    }
                    cur = d;
                }
                float za = z0[i], zb = z1[i];
#pragma unroll
                for (int k = 0; k < 6; k++) {
                    float yv = shYc[el][3 + k];
                    s0[k] += za * yv; s1[k] += zb * yv;
                }
            }
            size_t b = (size_t)cur * CHAN * NKC + 4;
#pragma unroll
            for (int k = 0; k < 6; k++) {
                atomicAdd(&A0[b + k], s0[k]);
                atomicAdd(&A1[b + k], s1[k]);
            }
        }
    }
}

// self-contraction + output; layer 0 also computes the layer-1 gate (fused k_gate).
// Layer-0 mixing GEMV uses packed f32x2 over padded sA rows.
__global__ void k_update(const float* __restrict__ Wmix, const float* __restrict__ Wsc,
                         const float* __restrict__ Wg,
                         const int* __restrict__ spec, float* __restrict__ out,
                         int layer, int N) {
    __shared__ __align__(16) float sA[CHAN * NKP];   // padded rows (48B, 16B-aligned)
    __shared__ float sh_o0[CHAN];
    int n = blockIdx.x;
    int d = threadIdx.x;
    for (int i = d; i < CHAN * NKC; i += CHAN) {
        int c = i / NKC, k = i - c * NKC;
        sA[c * NKP + k] = g_A[n * CHAN * NKC + i];
    }
    __syncthreads();
    for (int i = d; i < CHAN * NKC; i += CHAN) g_A[n * CHAN * NKC + i] = 0.f;

    const float* h0in = (layer == 0) ? g_h0a : g_h0b;
    float* h0out = (layer == 0) ? g_h0b : g_h0a;

    float A0d = sA[d * NKP];
    float A1d[3], A2c[6];
#pragma unroll
    for (int k = 0; k < 3; k++) A1d[k] = sA[d * NKP + 1 + k];
#pragma unroll
    for (int k = 0; k < 6; k++) A2c[k] = sA[d * NKP + 4 + k];

    const float* Wm = Wmix + layer * 3 * CHAN * CHAN;
    float mat0 = 0.f;
    float mat1[3] = {0.f, 0.f, 0.f};
    float mat2[6] = {0.f, 0.f, 0.f, 0.f, 0.f, 0.f};
    if (layer == 0) {
        // packed: pairs (k0,k1)(k2,k3)(k4,k5)(k6,k7)(k8,k9)
        unsigned long long a01 = 0ull, a23 = 0ull, a45 = 0ull, a67 = 0ull, a89 = 0ull;
        for (int c = 0; c < CHAN; c++) {
            const double2* rp = (const double2*)&sA[c * NKP];
            double2 r03 = rp[0];
            double2 r47 = rp[1];
            unsigned long long r89 = *(const unsigned long long*)&sA[c * NKP + 8];
            float w0 = Wm[c * CHAN + d];
            float w1 = Wm[CHAN * CHAN + c * CHAN + d];
            float w2 = Wm[2 * CHAN * CHAN + c * CHAN + d];
            unsigned long long w01 = pack2(w0, w1);
            unsigned long long w11 = pack2(w1, w1);
            unsigned long long w22 = pack2(w2, w2);
            a01 = ffma2(__double_as_longlong(r03.x), w01, a01);
            a23 = ffma2(__double_as_longlong(r03.y), w11, a23);
            a45 = ffma2(__double_as_longlong(r47.x), w22, a45);
            a67 = ffma2(__double_as_longlong(r47.y), w22, a67);
            a89 = ffma2(r89, w22, a89);
        }
        mat0    = __uint_as_float((unsigned)(a01 & 0xffffffffull));
        mat1[0] = __uint_as_float((unsigned)(a01 >> 32));
        mat1[1] = __uint_as_float((unsigned)(a23 & 0xffffffffull));
        mat1[2] = __uint_as_float((unsigned)(a23 >> 32));
        mat2[0] = __uint_as_float((unsigned)(a45 & 0xffffffffull));
        mat2[1] = __uint_as_float((unsigned)(a45 >> 32));
        mat2[2] = __uint_as_float((unsigned)(a67 & 0xffffffffull));
        mat2[3] = __uint_as_float((unsigned)(a67 >> 32));
        mat2[4] = __uint_as_float((unsigned)(a89 & 0xffffffffull));
        mat2[5] = __uint_as_float((unsigned)(a89 >> 32));
    } else {
        for (int c = 0; c < CHAN; c++)
            mat0 += sA[c * NKP] * Wm[c * CHAN + d];
    }
    float sq = A1d[0] * A1d[0] + A1d[1] * A1d[1] + A1d[2] * A1d[2]
             + A2c[0] * A2c[0] + A2c[3] * A2c[3] + A2c[5] * A2c[5]
             + 2.f * (A2c[1] * A2c[1] + A2c[2] * A2c[2] + A2c[4] * A2c[4]);

    int sp = spec[n];
    float sc0 = Wsc[layer * 10 * CHAN + sp * CHAN + d] * h0in[n * CHAN + d];
    float o0 = mat0 + sq + sc0;
    out[n * 128 + layer * CHAN + d] = o0;
    h0out[n * CHAN + d] = o0;

    if (layer == 0) {
        float m00 = A2c[0], m01 = A2c[1], m02 = A2c[2];
        float m11 = A2c[3], m12 = A2c[4], m22 = A2c[5];
        float v0 = mat1[0] + A0d * A1d[0] + m00 * A1d[0] + m01 * A1d[1] + m02 * A1d[2];
        float v1 = mat1[1] + A0d * A1d[1] + m01 * A1d[0] + m11 * A1d[1] + m12 * A1d[2];
        float v2 = mat1[2] + A0d * A1d[2] + m02 * A1d[0] + m12 * A1d[1] + m22 * A1d[2];
        g_h1[n * 3 * CHAN + 0 * CHAN + d] = v0;
        g_h1[n * 3 * CHAN + 1 * CHAN + d] = v1;
        g_h1[n * 3 * CHAN + 2 * CHAN + d] = v2;
        g_h2[n * 6 * CHAN + 0 * CHAN + d] = mat2[0] + A1d[0] * A1d[0] + A0d * m00;
        g_h2[n * 6 * CHAN + 1 * CHAN + d] = mat2[1] + A1d[0] * A1d[1] + A0d * m01;
        g_h2[n * 6 * CHAN + 2 * CHAN + d] = mat2[2] + A1d[0] * A1d[2] + A0d * m02;
        g_h2[n * 6 * CHAN + 3 * CHAN + d] = mat2[3] + A1d[1] * A1d[1] + A0d * m11;
        g_h2[n * 6 * CHAN + 4 * CHAN + d] = mat2[4] + A1d[1] * A1d[2] + A0d * m12;
        g_h2[n * 6 * CHAN + 5 * CHAN + d] = mat2[5] + A1d[2] * A1d[2] + A0d * m22;

        // fused gate for layer 1: s = o0(block) @ Wg[1]
        sh_o0[d] = o0;
        __syncthreads();
        const float* W = Wg + CHAN * CHAN;
        float acc = 0.f;
#pragma unroll 8
        for (int dd = 0; dd < CHAN; dd++) acc += sh_o0[dd] * W[dd * CHAN + d];
        g_s[n * CHAN + d] = acc;
    }
}

// ---------------- launch -----------------------------------------------------
extern "C" void kernel_launch(void* const* d_in, const int* in_sizes, int n_in,
                              void* d_out, int out_size) {
    const float* edge_vec = (const float*)d_in[0];
    const int*   species  = (const int*)d_in[1];
    const int*   eidx     = (const int*)d_in[2];
    const float* W_emb    = (const float*)d_in[3];
    const float* rw1      = (const float*)d_in[4];
    const float* rw2      = (const float*)d_in[5];
    const float* Wg       = (const float*)d_in[6];
    const float* Wsc      = (const float*)d_in[7];
    const float* Wmix     = (const float*)d_in[8];
    float* out = (float*)d_out;

    int E = in_sizes[0] / 3;
    int N = in_sizes[1];
    int GB_E = (E + 255) / 256;
    int GB_N = (N + 3) / 4;

    k_geomgate<<<GB_E + GB_N, 256>>>(edge_vec, species, W_emb, Wg, eidx,
                                     E, N, GB_E, GB_N);                    // 0
    k_scan<<<1, 1024>>>(N);                                                // 1
    k_place<<<GB_E, 256>>>(eidx, E);                                       // 2

    k_edge<<<E / 32, 384>>>(rw1, rw2, E, 0);                               // 3 <- profiled
    k_update<<<N, CHAN>>>(Wmix, Wsc, Wg, species, out, 0, N);              // 4
    k_edge<<<E / 32, 384>>>(rw1, rw2, E, 1);                               // 5
    k_update<<<N, CHAN>>>(Wmix, Wsc, Wg, species, out, 1, N);              // 6
}